// round 13
// baseline (speedup 1.0000x reference)
#include <cuda_runtime.h>
#include <cstdint>

// ---------------------------------------------------------------------------
// RPN target assignment, 2-kernel fused version.
// k_prep (1 block): mask-kind detect, first_valid scan, GT bin-sort, maxes.
// k_main: per-anchor windowed row scan -> writes match+bbox directly;
//         fused column argmax (smem u64 keys -> global RED.MAX);
//         last-block ticket applies pos_from_gt fixups + num_pos.
// Outputs (float32): rpn_match [A], rpn_bbox [A,4], num_pos [1]
// ---------------------------------------------------------------------------

#define MAX_A 262144
#define MAXG  512
#define TPB   256
#define NB    32
#define NBB   1024

__device__ int g_mask_kind;                  // 0=uint8, 1=int32, 2=float32
__device__ int g_ticket;                     // zero-init; self-resetting
__device__ int g_num_pos;
__device__ int g_first_valid;
__device__ int g_first_noncrowd;
__device__ unsigned g_maxgh_b, g_maxgw_b;    // max GT h/w (float bits)
__device__ int    g_gstart[NBB + 1];
__device__ float4 g_gbox[MAXG];
__device__ float  g_garea[MAXG];
__device__ int    g_gmeta[MAXG];             // orig g | (crowd ? 0x80000000 : 0)
__device__ unsigned long long g_colkey[MAXG];// zero-init; reset by ticket block
__device__ int g_fb[MAX_A];                  // bits0-3 flags, bits4+ best GT

__device__ __forceinline__ bool mask_at(const void* m, int kind, int i) {
    if (kind == 0) return ((const unsigned char*)m)[i] != 0;
    if (kind == 1) return ((const int*)m)[i] != 0;
    return ((const float*)m)[i] != 0.0f;
}

__device__ __forceinline__ int binOf(float v) {
    int b = (int)(v * 0.03125f);             // /32; callers pass v >= 0
    return b < 0 ? 0 : (b > NB - 1 ? NB - 1 : b);
}

// ------------------------------ prep kernel ---------------------------------
__global__ void __launch_bounds__(TPB) k_prep(const void* mask, int A,
        const int* __restrict__ gt_cls, const float4* __restrict__ gtb, int G) {
    __shared__ int s_h[NBB];
    __shared__ int s_scan[TPB];
    __shared__ int s_misc[8];   // 0:fnc 1:mh 2:mw 3:fv 4..7:nz
    const int t = threadIdx.x;

    if (t < 8) s_misc[t] = (t == 0 || t == 3) ? 0x7FFFFFFF : 0;
    for (int i = t; i < NBB; i += TPB) s_h[i] = 0;
    __syncthreads();

    // mask dtype detection on first min(A,1024) bytes (values are 0/1)
    {
        const unsigned char* p = (const unsigned char*)mask;
        int nbytes = A < 1024 ? A : 1024;
        for (int i = t; i < nbytes; i += TPB)
            if (p[i]) atomicAdd(&s_misc[4 + (i & 3)], 1);
    }
    // GT histogram + maxes + first non-crowd
    for (int g = t; g < G; g += TPB) {
        float4 b = gtb[g];
        atomicAdd(&s_h[binOf(b.x) * NB + binOf(b.y)], 1);
        atomicMax((unsigned*)&s_misc[1], __float_as_uint(b.z - b.x));
        atomicMax((unsigned*)&s_misc[2], __float_as_uint(b.w - b.y));
        if (gt_cls[g] >= 0) atomicMin(&s_misc[0], g);
    }
    __syncthreads();
    int kind;
    {
        int nz0 = s_misc[4], nz1 = s_misc[5], nz2 = s_misc[6], nz3 = s_misc[7];
        if (nz0 == 0 && (nz2 + nz3) > 0)            kind = 2;  // float32
        else if (nz1 == 0 && nz2 == 0 && nz3 == 0)  kind = 1;  // int32
        else                                        kind = 0;  // uint8/bool
    }
    // first_valid: scan mask in chunks from index 0 (expected 1 chunk)
    for (int base = 0; base < A; base += TPB) {
        int i = base + t;
        if (i < A && mask_at(mask, kind, i)) atomicMin(&s_misc[3], i);
        __syncthreads();
        int fv = s_misc[3];
        __syncthreads();
        if (fv != 0x7FFFFFFF) break;
    }
    // exclusive scan of s_h[NBB] (4 bins/thread)
    int base4 = t * 4;
    int c0 = s_h[base4], c1 = s_h[base4 + 1], c2 = s_h[base4 + 2], c3 = s_h[base4 + 3];
    int local = c0 + c1 + c2 + c3;
    s_scan[t] = local;
    __syncthreads();
    for (int off = 1; off < TPB; off <<= 1) {
        int v = (t >= off) ? s_scan[t - off] : 0;
        __syncthreads();
        s_scan[t] += v;
        __syncthreads();
    }
    int excl = s_scan[t] - local;
    s_h[base4]     = excl;
    s_h[base4 + 1] = excl + c0;
    s_h[base4 + 2] = excl + c0 + c1;
    s_h[base4 + 3] = excl + c0 + c1 + c2;
    g_gstart[base4]     = s_h[base4];
    g_gstart[base4 + 1] = s_h[base4 + 1];
    g_gstart[base4 + 2] = s_h[base4 + 2];
    g_gstart[base4 + 3] = s_h[base4 + 3];
    if (t == 0) g_gstart[NBB] = G;
    __syncthreads();
    // scatter GTs into bin-sorted arrays
    for (int g = t; g < G; g += TPB) {
        float4 b = gtb[g];
        bool crowd = gt_cls[g] < 0;
        int pos = atomicAdd(&s_h[binOf(b.x) * NB + binOf(b.y)], 1);
        g_gbox[pos]  = b;
        g_garea[pos] = (b.z - b.x) * (b.w - b.y);
        g_gmeta[pos] = g | (crowd ? 0x80000000 : 0);
    }
    if (t == 0) {
        g_mask_kind = kind;
        g_first_noncrowd = (s_misc[0] == 0x7FFFFFFF) ? 0 : s_misc[0];
        g_maxgh_b = (unsigned)s_misc[1];
        g_maxgw_b = (unsigned)s_misc[2];
        g_first_valid = s_misc[3];
        g_num_pos = 0;
    }
}

// ------------------------------ main kernel ---------------------------------
__global__ void __launch_bounds__(TPB) k_main(
    const float4* __restrict__ anchors, const void* __restrict__ mask,
    const int* __restrict__ gt_cls, const float4* __restrict__ gtb,
    const float* __restrict__ stddev, float* __restrict__ out,
    int A, int G)
{
    __shared__ float4 s_gb[MAXG];
    __shared__ float  s_ga[MAXG];
    __shared__ int    s_gm[MAXG];
    __shared__ int    s_gs[NBB + 1];
    __shared__ unsigned long long s_col[MAXG];
    __shared__ int s_last, s_cnt;

    const int t = threadIdx.x;
    const int kind = g_mask_kind;

    for (int i = t; i < G; i += TPB) {
        s_gb[i] = g_gbox[i]; s_ga[i] = g_garea[i]; s_gm[i] = g_gmeta[i];
        s_col[i] = 0ull;
    }
    for (int i = t; i < NBB + 1; i += TPB) s_gs[i] = g_gstart[i];
    if (t == 0) s_cnt = 0;
    __syncthreads();

    const int a = blockIdx.x * TPB + t;
    float4* __restrict__ bbox = reinterpret_cast<float4*>(out + A);
    bool pos_valid = false;

    if (a < A) {
        bool valid = mask_at(mask, kind, a);
        int match = 0;
        float4 d = make_float4(0.f, 0.f, 0.f, 0.f);
        if (valid) {
            float4 ab = anchors[a];
            float aarea = (ab.z - ab.x) * (ab.w - ab.y);
            float maxgh = __uint_as_float(g_maxgh_b);
            float maxgw = __uint_as_float(g_maxgw_b);
            // superset window: any GT with positive intersection satisfies
            // g.y1 in (a.y1 - maxgh, a.y2), g.x1 in (a.x1 - maxgw, a.x2)
            int by0 = binOf(fmaxf(ab.x - maxgh, 0.f)), by1 = binOf(ab.z);
            int bx0 = binOf(fmaxf(ab.y - maxgw, 0.f)), bx1 = binOf(ab.w);

            float biou = 0.f;                  // row best iou (non-crowd)
            int   bg   = g_first_noncrowd;     // row argmax default
            float cmax = 0.f;                  // crowd max iou
            unsigned akey = ~(unsigned)a;

            for (int by = by0; by <= by1; by++) {
                int s = s_gs[by * NB + bx0];
                int e = s_gs[by * NB + bx1 + 1];
                for (int i = s; i < e; i++) {
                    float4 gb = s_gb[i];
                    float iy1 = fmaxf(ab.x, gb.x);
                    float ix1 = fmaxf(ab.y, gb.y);
                    float iy2 = fminf(ab.z, gb.z);
                    float ix2 = fminf(ab.w, gb.w);
                    float inter = fmaxf(iy2 - iy1, 0.f) * fmaxf(ix2 - ix1, 0.f);
                    if (inter > 0.f) {
                        float iou = inter / ((aarea + s_ga[i]) - inter);  // same expr as ref
                        int m = s_gm[i];
                        if (m < 0) {
                            cmax = fmaxf(cmax, iou);
                        } else {
                            if (iou > biou) { biou = iou; bg = m; }
                            unsigned long long key =
                                ((unsigned long long)(__float_as_uint(iou) | 0x80000000u) << 32)
                                | (unsigned long long)akey;
                            atomicMax(&s_col[i], key);
                        }
                    }
                }
            }
            int fl = 0;
            if (biou >= 0.7f) fl |= 1;
            if (biou <  0.3f) fl |= 2;
            if (cmax <  0.001f) fl |= 4;       // no_crowd
            g_fb[a] = fl | (bg << 4);

            bool positive = (fl & 1) != 0;
            match = positive ? 1 : (((fl & 2) && (fl & 4)) ? -1 : 0);
            pos_valid = positive;
            if (positive) {
                float4 m = gtb[bg];
                // faithful to source bug: size = b[2:4] + b[0:2]
                float gsy = m.z + m.x,   gsx = m.w + m.y;
                float asy = ab.z + ab.x, asx = ab.w + ab.y;
                float gcy = gsy * 0.5f, gcx = gsx * 0.5f;
                float acy = asy * 0.5f, acx = asx * 0.5f;
                d.x = ((gcy - acy) / asy) / stddev[0];
                d.y = ((gcx - acx) / asx) / stddev[1];
                d.z = logf(gsy / asy) / stddev[2];
                d.w = logf(gsx / asx) / stddev[3];
            }
        }
        out[a] = (float)match;
        bbox[a] = d;
    }

    // block-level positive count
    unsigned bal = __ballot_sync(0xFFFFFFFFu, pos_valid);
    if ((t & 31) == 0 && bal) atomicAdd(&s_cnt, __popc(bal));
    __syncthreads();
    if (t == 0 && s_cnt) atomicAdd(&g_num_pos, s_cnt);

    // flush per-GT column keys to global (orig-g indexed)
    for (int i = t; i < G; i += TPB) {
        unsigned long long k = s_col[i];
        if (k) atomicMax(&g_colkey[s_gm[i] & 0x7FFFFFFF], k);
    }
    __syncthreads();

    // last-block ticket: pos_from_gt fixups + num_pos output + state reset
    if (t == 0) {
        __threadfence();
        int tk = atomicAdd(&g_ticket, 1);
        s_last = (tk == (int)gridDim.x - 1);
        if (s_last) g_ticket = 0;
    }
    __syncthreads();
    if (s_last) {
        int fv = g_first_valid;
        for (int g = t; g < G; g += TPB) {
            unsigned long long k = g_colkey[g];
            g_colkey[g] = 0ull;                          // reset for next launch
            if (gt_cls[g] < 0) continue;                 // crowd GT: no scatter
            unsigned idx = k ? ~(unsigned)(k & 0xFFFFFFFFull)
                             : (unsigned)((fv < A) ? fv : 0);
            if (idx >= (unsigned)A) continue;
            if (!mask_at(mask, kind, idx)) continue;     // invalid -> neutral anyway
            int old = atomicOr(&g_fb[idx], 8);
            if ((old & 9) == 0) {                        // newly positive
                atomicAdd(&g_num_pos, 1);
                out[idx] = 1.0f;
                float4 m  = gtb[old >> 4];
                float4 ab = anchors[idx];
                float gsy = m.z + m.x,   gsx = m.w + m.y;
                float asy = ab.z + ab.x, asx = ab.w + ab.y;
                float gcy = gsy * 0.5f, gcx = gsx * 0.5f;
                float acy = asy * 0.5f, acx = asx * 0.5f;
                float4 d;
                d.x = ((gcy - acy) / asy) / stddev[0];
                d.y = ((gcx - acx) / asx) / stddev[1];
                d.z = logf(gsy / asy) / stddev[2];
                d.w = logf(gsx / asx) / stddev[3];
                bbox[idx] = d;
            }
        }
        __syncthreads();
        if (t == 0) {
            __threadfence();
            out[5 * A] = (float)atomicAdd(&g_num_pos, 0);
        }
    }
}

// ------------------------------- launcher -----------------------------------
extern "C" void kernel_launch(void* const* d_in, const int* in_sizes, int n_in,
                              void* d_out, int out_size) {
    const float4* anchors = (const float4*)d_in[0];
    const void*   mask    = d_in[1];
    const int*    gt_cls  = (const int*)d_in[2];
    const float4* gtb     = (const float4*)d_in[3];
    const float*  stddev  = (const float*)d_in[4];
    int A = in_sizes[0] / 4;
    int G = in_sizes[2];
    float* out = (float*)d_out;
    int nb = (A + TPB - 1) / TPB;

    k_prep<<<1,  TPB>>>(mask, A, gt_cls, gtb, G);
    k_main<<<nb, TPB>>>(anchors, mask, gt_cls, gtb, stddev, out, A, G);
}

// round 15
// speedup vs baseline: 1.4226x; 1.4226x over previous
#include <cuda_runtime.h>
#include <cstdint>

// ---------------------------------------------------------------------------
// RPN target assignment, 4-kernel version with spatial GROUPING of anchors
// (bin-contiguous, order-free) for warp-coherent windowed IoU scans.
//   k_hist : per-block bin histogram of anchors
//   k_off  : per-bin offsets via single-counter base claim; +prep block
//   k_scat : scatter packed anchor records into bin groups
//   k_mainS: coherent row scan + fused column argmax + outputs + fixups
// Outputs (float32): rpn_match [A], rpn_bbox [A,4], num_pos [1]
// ---------------------------------------------------------------------------

#define MAX_A 262144
#define MAXG  512
#define TPB   256
#define NB    32
#define NBB   1024
#define NBLK  1024

__device__ int g_mask_kind;                  // 0=uint8, 1=int32, 2=float32
__device__ int g_ticket;                     // zero-init; self-resetting
__device__ int g_num_pos;
__device__ int g_abase;                      // zero-init; reset by ticket block
__device__ int g_first_valid;
__device__ int g_first_noncrowd;
__device__ unsigned g_maxgh_b, g_maxgw_b;    // max GT h/w (float bits)
__device__ int    g_gstart[NBB + 1];
__device__ float4 g_gbox[MAXG];
__device__ float  g_garea[MAXG];
__device__ int    g_gmeta[MAXG];             // orig g | (crowd ? 0x80000000 : 0)
__device__ int    g_bh[NBLK * NBB];          // per-(block,bin) counts -> offsets
__device__ float4 g_sbox[MAX_A];             // grouped anchor boxes
__device__ float2 g_smeta[MAX_A];            // (signed area, orig idx bits)
__device__ unsigned long long g_colkey[MAXG];// zero-init; reset by ticket block
__device__ int g_fb[MAX_A];                  // bits0-3 flags, bits4+ best GT

__device__ __forceinline__ bool mask_at(const void* m, int kind, int i) {
    if (kind == 0) return ((const unsigned char*)m)[i] != 0;
    if (kind == 1) return ((const int*)m)[i] != 0;
    return ((const float*)m)[i] != 0.0f;
}

__device__ __forceinline__ int binOf(float v) {
    int b = (int)(v * 0.03125f);             // /32; callers pass v >= 0
    return b < 0 ? 0 : (b > NB - 1 ? NB - 1 : b);
}

// ------------------------- anchor bin histogram -----------------------------
__global__ void __launch_bounds__(TPB) k_hist(const float4* __restrict__ anchors,
                                              int A) {
    __shared__ int sh[NBB];
    const int t = threadIdx.x;
    for (int i = t; i < NBB; i += TPB) sh[i] = 0;
    __syncthreads();
    int a = blockIdx.x * TPB + t;
    if (a < A) {
        float4 b = anchors[a];
        atomicAdd(&sh[binOf(b.x) * NB + binOf(b.y)], 1);
    }
    __syncthreads();
    reinterpret_cast<int4*>(g_bh + blockIdx.x * NBB)[t] =
        make_int4(sh[t * 4], sh[t * 4 + 1], sh[t * 4 + 2], sh[t * 4 + 3]);
}

// ------------- per-bin offsets (base claimed atomically) + prep -------------
__global__ void __launch_bounds__(TPB) k_off(int nb,
        const void* mask, int A,
        const int* __restrict__ gt_cls, const float4* __restrict__ gtb, int G) {
    __shared__ int s_h[NBB];
    __shared__ int s_scan[TPB];
    __shared__ int s_misc[8];    // 0:fnc 1:mh 2:mw 3:fv 4..7:nz
    __shared__ int s_base;
    const int t = threadIdx.x;

    if (blockIdx.x < NBB) {
        // scan this bin's per-block counts; claim contiguous output base
        const int bin = blockIdx.x;
        int v[4]; int loc = 0;
        #pragma unroll
        for (int i = 0; i < 4; i++) {
            int blk = t * 4 + i;
            v[i] = (blk < nb) ? g_bh[blk * NBB + bin] : 0;
            loc += v[i];
        }
        s_scan[t] = loc;
        __syncthreads();
        for (int off = 1; off < TPB; off <<= 1) {
            int x = (t >= off) ? s_scan[t - off] : 0;
            __syncthreads();
            s_scan[t] += x;
            __syncthreads();
        }
        if (t == TPB - 1) s_base = atomicAdd(&g_abase, s_scan[t]);  // bin total
        __syncthreads();
        int run = s_base + s_scan[t] - loc;
        #pragma unroll
        for (int i = 0; i < 4; i++) {
            int blk = t * 4 + i;
            if (blk < nb) g_bh[blk * NBB + bin] = run;
            run += v[i];
        }
        return;
    }

    // ---------------- prep block (blockIdx == NBB) ----------------
    if (t < 8) s_misc[t] = (t == 0 || t == 3) ? 0x7FFFFFFF : 0;
    for (int i = t; i < NBB; i += TPB) s_h[i] = 0;
    __syncthreads();
    // mask dtype detection on first min(A,1024) bytes (values are 0/1)
    {
        const unsigned char* p = (const unsigned char*)mask;
        int nbytes = A < 1024 ? A : 1024;
        for (int i = t; i < nbytes; i += TPB)
            if (p[i]) atomicAdd(&s_misc[4 + (i & 3)], 1);
    }
    // GT histogram + maxes + first non-crowd
    for (int g = t; g < G; g += TPB) {
        float4 b = gtb[g];
        atomicAdd(&s_h[binOf(b.x) * NB + binOf(b.y)], 1);
        atomicMax((unsigned*)&s_misc[1], __float_as_uint(b.z - b.x));
        atomicMax((unsigned*)&s_misc[2], __float_as_uint(b.w - b.y));
        if (gt_cls[g] >= 0) atomicMin(&s_misc[0], g);
    }
    __syncthreads();
    int kind;
    {
        int nz0 = s_misc[4], nz1 = s_misc[5], nz2 = s_misc[6], nz3 = s_misc[7];
        if (nz0 == 0 && (nz2 + nz3) > 0)            kind = 2;  // float32
        else if (nz1 == 0 && nz2 == 0 && nz3 == 0)  kind = 1;  // int32
        else                                        kind = 0;  // uint8/bool
    }
    // first_valid: scan mask chunks from index 0 (expected 1 chunk @90% valid)
    for (int base = 0; base < A; base += TPB) {
        int i = base + t;
        if (i < A && mask_at(mask, kind, i)) atomicMin(&s_misc[3], i);
        __syncthreads();
        int fv = s_misc[3];
        __syncthreads();
        if (fv != 0x7FFFFFFF) break;
    }
    // ordered exclusive scan of GT bins (4 bins/thread)
    int base4 = t * 4;
    int c0 = s_h[base4], c1 = s_h[base4 + 1], c2 = s_h[base4 + 2], c3 = s_h[base4 + 3];
    int local = c0 + c1 + c2 + c3;
    s_scan[t] = local;
    __syncthreads();
    for (int off = 1; off < TPB; off <<= 1) {
        int v = (t >= off) ? s_scan[t - off] : 0;
        __syncthreads();
        s_scan[t] += v;
        __syncthreads();
    }
    int excl = s_scan[t] - local;
    s_h[base4]     = excl;
    s_h[base4 + 1] = excl + c0;
    s_h[base4 + 2] = excl + c0 + c1;
    s_h[base4 + 3] = excl + c0 + c1 + c2;
    g_gstart[base4]     = s_h[base4];
    g_gstart[base4 + 1] = s_h[base4 + 1];
    g_gstart[base4 + 2] = s_h[base4 + 2];
    g_gstart[base4 + 3] = s_h[base4 + 3];
    if (t == 0) g_gstart[NBB] = G;
    __syncthreads();
    // scatter GTs into bin-sorted arrays (row-major bin order)
    for (int g = t; g < G; g += TPB) {
        float4 b = gtb[g];
        bool crowd = gt_cls[g] < 0;
        int pos = atomicAdd(&s_h[binOf(b.x) * NB + binOf(b.y)], 1);
        g_gbox[pos]  = b;
        g_garea[pos] = (b.z - b.x) * (b.w - b.y);
        g_gmeta[pos] = g | (crowd ? 0x80000000 : 0);
    }
    if (t == 0) {
        g_mask_kind = kind;
        g_first_noncrowd = (s_misc[0] == 0x7FFFFFFF) ? 0 : s_misc[0];
        g_maxgh_b = (unsigned)s_misc[1];
        g_maxgw_b = (unsigned)s_misc[2];
        g_first_valid = s_misc[3];
        g_num_pos = 0;
    }
}

// ------------------ scatter anchors into bin groups -------------------------
__global__ void __launch_bounds__(TPB) k_scat(const float4* __restrict__ anchors,
                                              const void* __restrict__ mask, int A) {
    __shared__ int s_off[NBB];
    const int t = threadIdx.x;
    int4 o = reinterpret_cast<const int4*>(g_bh + blockIdx.x * NBB)[t];
    s_off[t * 4]     = o.x;
    s_off[t * 4 + 1] = o.y;
    s_off[t * 4 + 2] = o.z;
    s_off[t * 4 + 3] = o.w;
    __syncthreads();
    int a = blockIdx.x * TPB + t;
    if (a >= A) return;
    float4 b = anchors[a];
    int bin = binOf(b.x) * NB + binOf(b.y);
    int p = atomicAdd(&s_off[bin], 1);
    float area = (b.z - b.x) * (b.w - b.y);
    bool valid = mask_at(mask, g_mask_kind, a);
    g_sbox[p]  = b;
    g_smeta[p] = make_float2(valid ? area : -area, __int_as_float(a));
}

// ---------------- main: coherent row scan + fused col argmax ----------------
__global__ void __launch_bounds__(TPB) k_mainS(
    const float4* __restrict__ anchors, const void* __restrict__ mask,
    const int* __restrict__ gt_cls, const float4* __restrict__ gtb,
    const float* __restrict__ stddev, float* __restrict__ out,
    int A, int G)
{
    __shared__ float4 s_gb[MAXG];
    __shared__ float  s_ga[MAXG];
    __shared__ int    s_gm[MAXG];
    __shared__ int    s_gs[NBB + 1];
    __shared__ unsigned long long s_col[MAXG];
    __shared__ int s_last, s_cnt;

    const int t = threadIdx.x;
    for (int i = t; i < G; i += TPB) {
        s_gb[i] = g_gbox[i]; s_ga[i] = g_garea[i]; s_gm[i] = g_gmeta[i];
        s_col[i] = 0ull;
    }
    for (int i = t; i < NBB + 1; i += TPB) s_gs[i] = g_gstart[i];
    if (t == 0) s_cnt = 0;
    __syncthreads();

    const int p = blockIdx.x * TPB + t;
    float4* __restrict__ bbox = reinterpret_cast<float4*>(out + A);
    bool pos_valid = false;

    if (p < A) {
        float2 mt = g_smeta[p];
        float aarea = mt.x;
        int orig = __float_as_int(mt.y);
        int match = 0;
        float4 d = make_float4(0.f, 0.f, 0.f, 0.f);
        if (aarea > 0.f) {                        // valid anchor
            float4 ab = g_sbox[p];
            float maxgh = __uint_as_float(g_maxgh_b);
            float maxgw = __uint_as_float(g_maxgw_b);
            // superset window: any GT with positive intersection satisfies
            // g.y1 in (a.y1 - maxgh, a.y2), g.x1 in (a.x1 - maxgw, a.x2)
            int by0 = binOf(fmaxf(ab.x - maxgh, 0.f)), by1 = binOf(ab.z);
            int bx0 = binOf(fmaxf(ab.y - maxgw, 0.f)), bx1 = binOf(ab.w);

            float biou = 0.f;                     // row best iou (non-crowd)
            int   bg   = g_first_noncrowd;        // row argmax default
            float cmax = 0.f;                     // crowd max iou
            unsigned akey = ~(unsigned)orig;

            for (int by = by0; by <= by1; by++) {
                int s = s_gs[by * NB + bx0];
                int e = s_gs[by * NB + bx1 + 1];
                for (int i = s; i < e; i++) {
                    float4 gb = s_gb[i];          // broadcast: lanes share i
                    float iy1 = fmaxf(ab.x, gb.x);
                    float ix1 = fmaxf(ab.y, gb.y);
                    float iy2 = fminf(ab.z, gb.z);
                    float ix2 = fminf(ab.w, gb.w);
                    float inter = fmaxf(iy2 - iy1, 0.f) * fmaxf(ix2 - ix1, 0.f);
                    if (inter > 0.f) {
                        float iou = inter / ((aarea + s_ga[i]) - inter);  // ref expr
                        int m = s_gm[i];
                        if (m < 0) {
                            cmax = fmaxf(cmax, iou);
                        } else {
                            if (iou > biou) { biou = iou; bg = m; }
                            unsigned long long key =
                                ((unsigned long long)(__float_as_uint(iou) | 0x80000000u) << 32)
                                | (unsigned long long)akey;
                            atomicMax(&s_col[i], key);
                        }
                    }
                }
            }
            int fl = 0;
            if (biou >= 0.7f) fl |= 1;
            if (biou <  0.3f) fl |= 2;
            if (cmax <  0.001f) fl |= 4;          // no_crowd
            g_fb[orig] = fl | (bg << 4);

            bool positive = (fl & 1) != 0;
            match = positive ? 1 : (((fl & 2) && (fl & 4)) ? -1 : 0);
            pos_valid = positive;
            if (positive) {
                float4 m = gtb[bg];
                // faithful to source bug: size = b[2:4] + b[0:2]
                float gsy = m.z + m.x,   gsx = m.w + m.y;
                float asy = ab.z + ab.x, asx = ab.w + ab.y;
                float gcy = gsy * 0.5f, gcx = gsx * 0.5f;
                float acy = asy * 0.5f, acx = asx * 0.5f;
                d.x = ((gcy - acy) / asy) / stddev[0];
                d.y = ((gcx - acx) / asx) / stddev[1];
                d.z = logf(gsy / asy) / stddev[2];
                d.w = logf(gsx / asx) / stddev[3];
            }
        }
        out[orig] = (float)match;
        bbox[orig] = d;
    }

    // block-level positive count
    unsigned bal = __ballot_sync(0xFFFFFFFFu, pos_valid);
    if ((t & 31) == 0 && bal) atomicAdd(&s_cnt, __popc(bal));
    __syncthreads();
    if (t == 0 && s_cnt) atomicAdd(&g_num_pos, s_cnt);

    // flush per-GT column keys to global (orig-g indexed)
    for (int i = t; i < G; i += TPB) {
        unsigned long long k = s_col[i];
        if (k) atomicMax(&g_colkey[s_gm[i] & 0x7FFFFFFF], k);
    }
    __syncthreads();

    // last-block ticket: pos_from_gt fixups + num_pos output + state reset
    if (t == 0) {
        __threadfence();
        int tk = atomicAdd(&g_ticket, 1);
        s_last = (tk == (int)gridDim.x - 1);
        if (s_last) { g_ticket = 0; g_abase = 0; }
    }
    __syncthreads();
    if (s_last) {
        const int kind = g_mask_kind;
        int fv = g_first_valid;
        for (int g = t; g < G; g += TPB) {
            unsigned long long k = g_colkey[g];
            g_colkey[g] = 0ull;                          // reset for next launch
            if (gt_cls[g] < 0) continue;                 // crowd GT: no scatter
            unsigned idx = k ? ~(unsigned)(k & 0xFFFFFFFFull)
                             : (unsigned)((fv < A) ? fv : 0);
            if (idx >= (unsigned)A) continue;
            if (!mask_at(mask, kind, idx)) continue;     // invalid -> neutral anyway
            int old = atomicOr(&g_fb[idx], 8);
            if ((old & 9) == 0) {                        // newly positive
                atomicAdd(&g_num_pos, 1);
                out[idx] = 1.0f;
                float4 m  = gtb[old >> 4];
                float4 ab = anchors[idx];
                float gsy = m.z + m.x,   gsx = m.w + m.y;
                float asy = ab.z + ab.x, asx = ab.w + ab.y;
                float gcy = gsy * 0.5f, gcx = gsx * 0.5f;
                float acy = asy * 0.5f, acx = asx * 0.5f;
                float4 d;
                d.x = ((gcy - acy) / asy) / stddev[0];
                d.y = ((gcx - acx) / asx) / stddev[1];
                d.z = logf(gsy / asy) / stddev[2];
                d.w = logf(gsx / asx) / stddev[3];
                bbox[idx] = d;
            }
        }
        __syncthreads();
        if (t == 0) {
            __threadfence();
            out[5 * A] = (float)atomicAdd(&g_num_pos, 0);
        }
    }
}

// ------------------------------- launcher -----------------------------------
extern "C" void kernel_launch(void* const* d_in, const int* in_sizes, int n_in,
                              void* d_out, int out_size) {
    const float4* anchors = (const float4*)d_in[0];
    const void*   mask    = d_in[1];
    const int*    gt_cls  = (const int*)d_in[2];
    const float4* gtb     = (const float4*)d_in[3];
    const float*  stddev  = (const float*)d_in[4];
    int A = in_sizes[0] / 4;
    int G = in_sizes[2];
    float* out = (float*)d_out;
    int nb = (A + TPB - 1) / TPB;

    k_hist <<<nb,      TPB>>>(anchors, A);
    k_off  <<<NBB + 1, TPB>>>(nb, mask, A, gt_cls, gtb, G);
    k_scat <<<nb,      TPB>>>(anchors, mask, A);
    k_mainS<<<nb,      TPB>>>(anchors, mask, gt_cls, gtb, stddev, out, A, G);
}